// round 5
// baseline (speedup 1.0000x reference)
#include <cuda_runtime.h>
#include <math.h>

#define N_FFT   16384
#define L_SIG   8192
#define D_DIM   1024
#define BSZ     4
#define THREADS 256

// Pad-by-1-per-64-elems layout: conflict-free (2-phase) for strides 1,4,64,256.
#define PHYS(i) ((i) + ((i) >> 6))
#define SMEM_ELEMS (N_FFT + N_FFT / 64)   // 16640 float2 = 133120 B

__device__ float2 d_tw[N_FFT / 4];                   // exp(-2*pi*i*k/N), k < N/4
__device__ float4 d_Hf4[(size_t)D_DIM * N_FFT / 2];  // spectra of h + B*delta0 (s-index order)
__device__ unsigned d_flags[D_DIM];

__device__ __forceinline__ float2 cmul(float2 a, float2 b) {
    return make_float2(a.x * b.x - a.y * b.y, a.x * b.y + a.y * b.x);
}

__global__ void init_kernel() {
    int k = blockIdx.x * blockDim.x + threadIdx.x;
    if (k < N_FFT / 4) {
        double ang = -2.0 * 3.14159265358979323846 * (double)k / (double)N_FFT;
        d_tw[k] = make_float2((float)cos(ang), (float)sin(ang));
    }
    if (k < D_DIM) d_flags[k] = 0u;
}

// DIF radix-4 butterfly, twiddles on outputs
__device__ __forceinline__ void dif4(float2& a0, float2& a1, float2& a2, float2& a3, float2 w1) {
    float2 t0 = make_float2(a0.x + a2.x, a0.y + a2.y);
    float2 t1 = make_float2(a0.x - a2.x, a0.y - a2.y);
    float2 t2 = make_float2(a1.x + a3.x, a1.y + a3.y);
    float2 t3 = make_float2(a1.x - a3.x, a1.y - a3.y);
    float2 b0 = make_float2(t0.x + t2.x, t0.y + t2.y);
    float2 b2 = make_float2(t0.x - t2.x, t0.y - t2.y);
    float2 b1 = make_float2(t1.x + t3.y, t1.y - t3.x);   // t1 - i*t3
    float2 b3 = make_float2(t1.x - t3.y, t1.y + t3.x);   // t1 + i*t3
    float2 w2 = cmul(w1, w1), w3 = cmul(w1, w2);
    a0 = b0; a1 = cmul(b1, w1); a2 = cmul(b2, w2); a3 = cmul(b3, w3);
}
__device__ __forceinline__ void dif4_nt(float2& a0, float2& a1, float2& a2, float2& a3) {
    float2 t0 = make_float2(a0.x + a2.x, a0.y + a2.y);
    float2 t1 = make_float2(a0.x - a2.x, a0.y - a2.y);
    float2 t2 = make_float2(a1.x + a3.x, a1.y + a3.y);
    float2 t3 = make_float2(a1.x - a3.x, a1.y - a3.y);
    a0 = make_float2(t0.x + t2.x, t0.y + t2.y);
    a2 = make_float2(t0.x - t2.x, t0.y - t2.y);
    a1 = make_float2(t1.x + t3.y, t1.y - t3.x);
    a3 = make_float2(t1.x - t3.y, t1.y + t3.x);
}

// DIT radix-4 inverse butterfly, (pre-conjugated) twiddles on inputs
__device__ __forceinline__ void dit4(float2& c0, float2& c1, float2& c2, float2& c3, float2 w1) {
    float2 w2 = cmul(w1, w1), w3 = cmul(w1, w2);
    float2 a1 = cmul(c1, w1), a2 = cmul(c2, w2), a3 = cmul(c3, w3);
    float2 u0 = make_float2(c0.x + a2.x, c0.y + a2.y);
    float2 u1 = make_float2(c0.x - a2.x, c0.y - a2.y);
    float2 u2 = make_float2(a1.x + a3.x, a1.y + a3.y);
    float2 u3 = make_float2(a1.x - a3.x, a1.y - a3.y);
    c0 = make_float2(u0.x + u2.x, u0.y + u2.y);
    c1 = make_float2(u1.x - u3.y, u1.y + u3.x);  // u1 + i*u3
    c2 = make_float2(u0.x - u2.x, u0.y - u2.y);
    c3 = make_float2(u1.x + u3.y, u1.y - u3.x);  // u1 - i*u3
}
__device__ __forceinline__ void dit4_nt(float2& c0, float2& c1, float2& c2, float2& c3) {
    float2 u0 = make_float2(c0.x + c2.x, c0.y + c2.y);
    float2 u1 = make_float2(c0.x - c2.x, c0.y - c2.y);
    float2 u2 = make_float2(c1.x + c3.x, c1.y + c3.y);
    float2 u3 = make_float2(c1.x - c3.x, c1.y - c3.y);
    c0 = make_float2(u0.x + u2.x, u0.y + u2.y);
    c1 = make_float2(u1.x - u3.y, u1.y + u3.x);
    c2 = make_float2(u0.x - u2.x, u0.y - u2.y);
    c3 = make_float2(u1.x + u3.y, u1.y - u3.x);
}
// inv q=4096 butterfly, only outputs 0 and q needed
__device__ __forceinline__ void dit4_lo(float2 c0, float2 c1, float2 c2, float2 c3, float2 w1,
                                        float2& o0, float2& o1) {
    float2 w2 = cmul(w1, w1), w3 = cmul(w1, w2);
    float2 a1 = cmul(c1, w1), a2 = cmul(c2, w2), a3 = cmul(c3, w3);
    float2 u0 = make_float2(c0.x + a2.x, c0.y + a2.y);
    float2 u1 = make_float2(c0.x - a2.x, c0.y - a2.y);
    float2 u2 = make_float2(a1.x + a3.x, a1.y + a3.y);
    float2 u3 = make_float2(a1.x - a3.x, a1.y - a3.y);
    o0 = make_float2(u0.x + u2.x, u0.y + u2.y);
    o1 = make_float2(u1.x - u3.y, u1.y + u3.x);
}

// ---- G0 core: fwd layers q=4096 (zero-padded 2-input), 1024, 256 on e[64] (stride 256, j = tid)
__device__ __forceinline__ void g0_layers(float2 e[64], int j) {
#pragma unroll
    for (int c = 0; c < 16; ++c) {          // q=4096, a2=a3=0
        float2 a0 = e[c], a1 = e[c + 16];
        float2 b0 = make_float2(a0.x + a1.x, a0.y + a1.y);
        float2 b2 = make_float2(a0.x - a1.x, a0.y - a1.y);
        float2 b1 = make_float2(a0.x + a1.y, a0.y - a1.x);   // a0 - i*a1
        float2 b3 = make_float2(a0.x - a1.y, a0.y + a1.x);   // a0 + i*a1
        float2 w1 = d_tw[j + (c << 8)];
        float2 w2 = cmul(w1, w1), w3 = cmul(w1, w2);
        e[c]      = b0;
        e[c + 16] = cmul(b1, w1);
        e[c + 32] = cmul(b2, w2);
        e[c + 48] = cmul(b3, w3);
    }
#pragma unroll
    for (int c = 0; c < 4; ++c) {           // q=1024
        float2 w = d_tw[(j + (c << 8)) << 2];
#pragma unroll
        for (int g = 0; g < 4; ++g)
            dif4(e[16 * g + c], e[16 * g + c + 4], e[16 * g + c + 8], e[16 * g + c + 12], w);
    }
    {
        float2 w = d_tw[j << 4];            // q=256
#pragma unroll
        for (int g = 0; g < 16; ++g)
            dif4(e[4 * g], e[4 * g + 1], e[4 * g + 2], e[4 * g + 3], w);
    }
}

// ---- P1: fwd q=64,16,4 (Q=4)
__device__ __forceinline__ void pass1(float2* s) {
    const int G = threadIdx.x;
    const int j = G & 3;
    const int base = (G >> 2) << 8;
    float2 e[64];
#pragma unroll
    for (int u = 0; u < 64; ++u) e[u] = s[PHYS(base + j + (u << 2))];
#pragma unroll
    for (int c = 0; c < 16; ++c) {          // q=64
        float2 w = d_tw[(j + 4 * c) << 6];
        dif4(e[c], e[c + 16], e[c + 32], e[c + 48], w);
    }
#pragma unroll
    for (int c = 0; c < 4; ++c) {           // q=16
        float2 w = d_tw[(j + 4 * c) << 8];
#pragma unroll
        for (int g = 0; g < 4; ++g)
            dif4(e[16 * g + c], e[16 * g + c + 4], e[16 * g + c + 8], e[16 * g + c + 12], w);
    }
    {
        float2 w = d_tw[j << 10];           // q=4
#pragma unroll
        for (int g = 0; g < 16; ++g)
            dif4(e[4 * g], e[4 * g + 1], e[4 * g + 2], e[4 * g + 3], w);
    }
#pragma unroll
    for (int u = 0; u < 64; ++u) s[PHYS(base + j + (u << 2))] = e[u];
}

// ---- P3: inv q=64,256,1024 (Q=64)
__device__ __forceinline__ void pass3(float2* s) {
    const int G = threadIdx.x;
    const int j = G & 63;
    const int base = (G >> 6) << 12;
    float2 e[64];
#pragma unroll
    for (int u = 0; u < 64; ++u) e[u] = s[PHYS(base + j + (u << 6))];
    {
        float2 w = d_tw[j << 6]; w.y = -w.y;     // q=64
#pragma unroll
        for (int g = 0; g < 16; ++g)
            dit4(e[4 * g], e[4 * g + 1], e[4 * g + 2], e[4 * g + 3], w);
    }
#pragma unroll
    for (int c = 0; c < 4; ++c) {                // q=256
        float2 w = d_tw[(j + (c << 6)) << 4]; w.y = -w.y;
#pragma unroll
        for (int g = 0; g < 4; ++g)
            dit4(e[16 * g + c], e[16 * g + c + 4], e[16 * g + c + 8], e[16 * g + c + 12], w);
    }
#pragma unroll
    for (int c = 0; c < 16; ++c) {               // q=1024
        float2 w = d_tw[(j + (c << 6)) << 2]; w.y = -w.y;
        dit4(e[c], e[c + 16], e[c + 32], e[c + 48], w);
    }
#pragma unroll
    for (int u = 0; u < 64; ++u) s[PHYS(base + j + (u << 6))] = e[u];
}

// ---------------- fused kernel: bids [0,1024) produce Hf rows; rest consume
__global__ __launch_bounds__(THREADS, 1) void fftconv_kernel(const float* __restrict__ h,
                                                             const float* __restrict__ x,
                                                             const float* __restrict__ Bp,
                                                             float* __restrict__ y) {
    extern __shared__ float2 s[];
    const int bid = blockIdx.x;
    const int tid = threadIdx.x;

    if (bid < D_DIM) {
        // ============ producer: spectrum of h_eff = h + B*delta0 ============
        const int d = bid;
        const float* hr = h + (size_t)d * L_SIG;
        const float Bv = Bp[d];
        {   // G0: fwd q=4096,1024,256 from global (real input, zero-padded)
            const int j = tid;
            float2 e[64];
#pragma unroll
            for (int u = 0; u < 32; ++u) {
                float v = hr[j + (u << 8)];
                if (u == 0 && j == 0) v += Bv;       // fold B*x into the filter
                e[u] = make_float2(v, 0.f);
            }
#pragma unroll
            for (int u = 32; u < 64; ++u) e[u] = make_float2(0.f, 0.f);
            g0_layers(e, j);
#pragma unroll
            for (int u = 0; u < 64; ++u) s[PHYS(j + (u << 8))] = e[u];
        }
        __syncthreads();
        pass1(s);
        __syncthreads();
        {   // P2p: fwd q=1 + store Hf (thread-chunk order = s-index order)
            const int base = tid << 6;
            float2 e[64];
#pragma unroll
            for (int u = 0; u < 64; ++u) e[u] = s[PHYS(base + u)];
#pragma unroll
            for (int g = 0; g < 16; ++g)
                dif4_nt(e[4 * g], e[4 * g + 1], e[4 * g + 2], e[4 * g + 3]);
            float4* out4 = d_Hf4 + ((size_t)d * N_FFT + base) / 2;
#pragma unroll
            for (int v = 0; v < 32; ++v)
                out4[v] = make_float4(e[2 * v].x, e[2 * v].y, e[2 * v + 1].x, e[2 * v + 1].y);
        }
        __syncthreads();
        if (tid == 0) {
            __threadfence();
            atomicExch(&d_flags[d], 1u);
        }
    } else {
        // ============ consumer: batch-packed conv ============
        const int c = bid - D_DIM;
        const int d = c >> 1;
        const int p = c & 1;
        const float* x0 = x + ((size_t)(2 * p) * D_DIM + d) * L_SIG;
        const float* x1 = x + ((size_t)(2 * p + 1) * D_DIM + d) * L_SIG;
        float* y0       = y + ((size_t)(2 * p) * D_DIM + d) * L_SIG;
        float* y1       = y + ((size_t)(2 * p + 1) * D_DIM + d) * L_SIG;

        {   // G0: fwd q=4096,1024,256 from global (z = x0 + i*x1, zero-padded)
            const int j = tid;
            float2 e[64];
#pragma unroll
            for (int u = 0; u < 32; ++u) {
                int n = j + (u << 8);
                e[u] = make_float2(x0[n], x1[n]);
            }
#pragma unroll
            for (int u = 32; u < 64; ++u) e[u] = make_float2(0.f, 0.f);
            g0_layers(e, j);
#pragma unroll
            for (int u = 0; u < 64; ++u) s[PHYS(j + (u << 8))] = e[u];
        }
        __syncthreads();
        pass1(s);
        __syncthreads();

        // wait for Hf row d (producers have strictly lower bids -> progress guaranteed)
        if (tid == 0) {
            while (atomicAdd(&d_flags[d], 0u) == 0u) __nanosleep(64);
        }
        __syncthreads();
        __threadfence();   // acquire for Hf reads

        {   // P2: fwd q=1 + pointwise Hf/N + inv q=1,4,16
            const int base = tid << 6;
            const float4* H4 = d_Hf4 + ((size_t)d * N_FFT + base) / 2;
            const float scale = 1.0f / (float)N_FFT;
            float2 e[64];
#pragma unroll
            for (int u = 0; u < 64; ++u) e[u] = s[PHYS(base + u)];
#pragma unroll
            for (int g = 0; g < 16; ++g)          // fwd q=1
                dif4_nt(e[4 * g], e[4 * g + 1], e[4 * g + 2], e[4 * g + 3]);
#pragma unroll
            for (int v = 0; v < 32; ++v) {        // pointwise
                float4 hv = H4[v];
                float2 p0 = cmul(e[2 * v],     make_float2(hv.x, hv.y));
                float2 p1 = cmul(e[2 * v + 1], make_float2(hv.z, hv.w));
                e[2 * v]     = make_float2(p0.x * scale, p0.y * scale);
                e[2 * v + 1] = make_float2(p1.x * scale, p1.y * scale);
            }
#pragma unroll
            for (int g = 0; g < 16; ++g)          // inv q=1
                dit4_nt(e[4 * g], e[4 * g + 1], e[4 * g + 2], e[4 * g + 3]);
#pragma unroll
            for (int c2 = 0; c2 < 4; ++c2) {      // inv q=4
                float2 w = d_tw[c2 << 10]; w.y = -w.y;
#pragma unroll
                for (int g = 0; g < 4; ++g)
                    dit4(e[16 * g + c2], e[16 * g + c2 + 4], e[16 * g + c2 + 8], e[16 * g + c2 + 12], w);
            }
#pragma unroll
            for (int m = 0; m < 16; ++m) {        // inv q=16
                float2 w = d_tw[m << 8]; w.y = -w.y;
                dit4(e[m], e[m + 16], e[m + 32], e[m + 48], w);
            }
#pragma unroll
            for (int u = 0; u < 64; ++u) s[PHYS(base + u)] = e[u];
        }
        __syncthreads();
        pass3(s);
        __syncthreads();

        {   // P4: inv q=4096 + y store (upper garbage half never computed)
            const int j = tid;
            float2 e[64];
#pragma unroll
            for (int u = 0; u < 64; ++u) e[u] = s[PHYS(j + (u << 8))];
#pragma unroll
            for (int c2 = 0; c2 < 16; ++c2) {
                float2 w = d_tw[j + (c2 << 8)]; w.y = -w.y;
                float2 o0, o1;
                dit4_lo(e[c2], e[c2 + 16], e[c2 + 32], e[c2 + 48], w, o0, o1);
                int n = j + (c2 << 8);
                y0[n]        = o0.x;
                y1[n]        = o0.y;
                y0[n + 4096] = o1.x;
                y1[n + 4096] = o1.y;
            }
        }
    }
}

extern "C" void kernel_launch(void* const* d_in, const int* in_sizes, int n_in,
                              void* d_out, int out_size) {
    const float* h = (const float*)d_in[0];
    const float* x = (const float*)d_in[1];
    const float* B = (const float*)d_in[2];
    float* y = (float*)d_out;

    const size_t smem = (size_t)SMEM_ELEMS * sizeof(float2);  // 133120 B
    cudaFuncSetAttribute(fftconv_kernel, cudaFuncAttributeMaxDynamicSharedMemorySize, (int)smem);

    init_kernel<<<16, 256>>>();
    fftconv_kernel<<<D_DIM + D_DIM * (BSZ / 2), THREADS, smem>>>(h, x, B, y);
}